// round 17
// baseline (speedup 1.0000x reference)
#include <cuda_runtime.h>
#include <cuda_bf16.h>

// PositionalEncoding: out[p][j] = X[p][j] + (j even ? sin(p*w_j) : cos(p*w_j))
//   w_j = 10000^{-(j + (j%2))/n},  n = 4096, m = 8192 rows.
//
// FINAL CANDIDATE (R17 = R16 optimum with read-only-path loads):
//  * Transcendentals amortized via angle-addition recurrence along rows:
//      s' = s*cw + c*sw,  c' = c*cw - s*sw
//    with shared-frequency compression: cols 4cv+{0,1,2,3} have exponents
//    (4cv+{0,2,2,4})/n -> 3 distinct frequencies -> 3 states/thread.
//  * Register-resident load batching: 16 LDG.128 held live per thread
//    (regs=96, occ ~26%) — measured knee of the MLP-vs-occupancy curve.
//  * Loads via ld.global.nc (__ldg) read-only path; stores streaming (.cs).
//  * Converged at the mixed read/write HBM ceiling: ~7.4 TB/s app-effective
//    (~92% of 8 TB/s spec); kernel 36.3us, all other levers measured neutral.

#define PE_M     8192
#define PE_N     4096
#define PE_NV4   (PE_N / 4)      // 1024 float4 per row
#define PE_ROWS  16              // rows per thread (all batch-loaded)
#define PE_TPB   128             // threads per block (column-quads)

__global__ __launch_bounds__(PE_TPB)
void pe_kernel(const float4* __restrict__ X, float4* __restrict__ Out) {
    const int cv   = blockIdx.x * PE_TPB + threadIdx.x;  // column-quad index, 0..1023
    const int row0 = blockIdx.y * PE_ROWS;

    const float L2_10K = 13.287712379549449f;  // log2(10000)

    // 3 distinct frequencies per quad: exponents (4cv + 2t)/n, t = 0,1,2
    float s[3], c[3], sw[3], cw[3];
#pragma unroll
    for (int t = 0; t < 3; t++) {
        const float e = (float)(4 * cv + 2 * t) * (1.0f / (float)PE_N);
        const float w = exp2f(-e * L2_10K);           // 10000^{-e}
        sincosf((float)row0 * w, &s[t], &c[t]);       // precise: angle up to ~8191
        __sincosf(w, &sw[t], &cw[t]);                 // fast: w in (0, 1]
    }

    const float4* __restrict__ xp = X   + (size_t)row0 * PE_NV4 + cv;
    float4*       __restrict__ yp = Out + (size_t)row0 * PE_NV4 + cv;

    // Batch all 16 loads — register-resident, read-only path.
    float4 v[PE_ROWS];
#pragma unroll
    for (int r = 0; r < PE_ROWS; r++)
        v[r] = __ldg(xp + (size_t)r * PE_NV4);

    // Add table values; advance rotation per row.
    // cols 4cv+{0,1,2,3}: sin(w0), cos(w1), sin(w1), cos(w2)
#pragma unroll
    for (int r = 0; r < PE_ROWS; r++) {
        v[r].x += s[0];
        v[r].y += c[1];
        v[r].z += s[1];
        v[r].w += c[2];
#pragma unroll
        for (int t = 0; t < 3; t++) {
            const float ns = fmaf(s[t], cw[t],  c[t] * sw[t]);
            const float nc = fmaf(c[t], cw[t], -s[t] * sw[t]);
            s[t] = ns; c[t] = nc;
        }
    }

    // Streaming stores (write-once, evict-first).
#pragma unroll
    for (int r = 0; r < PE_ROWS; r++)
        __stcs(yp + (size_t)r * PE_NV4, v[r]);
}

extern "C" void kernel_launch(void* const* d_in, const int* in_sizes, int n_in,
                              void* d_out, int out_size) {
    (void)in_sizes; (void)n_in; (void)out_size;
    const float4* X   = (const float4*)d_in[0];
    float4*       Out = (float4*)d_out;

    dim3 block(PE_TPB);
    dim3 grid(PE_NV4 / PE_TPB, PE_M / PE_ROWS);   // (8, 512) = 4096 CTAs
    pe_kernel<<<grid, block>>>(X, Out);
}